// round 7
// baseline (speedup 1.0000x reference)
#include <cuda_runtime.h>
#include <cstdint>

// ---------------------------------------------------------------------------
// SphericalExpansion, round 7 = round 4 (best) + occupancy 6/SM + exp2f trim.
//
// One WARP per 4-edge pack. Lane L:
//   - computes rb[k=L] = exp2(K2E (r-center_L)^2)*... (k = l*8+n)
//   - computes Y[lm=L&15] = f1*f2 (branchless coefficient tables)
//   - owns the segment floats {L, L+32, L+64, L+96}: all have lm = L&15
//     (its OWN Y) and n = (L>>4)+2k -> 4 rb gathered via shfl.idx
//   - 4x red.global.add.f32 at [p], [p+32], [p+64], [p+96]: each covers one
//     contiguous 128B wavefront across the warp
// Batch loads per pack: float4/int4 (10 LDGs for 4 edges).
// Cutoff strictly branchless (saturate + cospif) — R6 showed per-edge
// if{} costs ~150us in BSSY/BSYNC overhead.
// ---------------------------------------------------------------------------

__constant__ float cA[16][4] = {   // f1 = a0 + ax*x + ay*y + az*z (one-hot)
    {1,0,0,0}, {0,0,1,0}, {0,0,0,1}, {0,1,0,0},
    {1,0,0,0}, {1,0,0,0}, {1,0,0,0}, {1,0,0,0},
    {1,0,0,0}, {0,0,1,0}, {0,1,0,0}, {0,0,1,0},
    {0,0,0,1}, {0,1,0,0}, {0,0,0,1}, {0,1,0,0},
};

__constant__ float cF[16][7] = {   // f2 = c0+cx*x2+cy*y2+cz*z2+cxy*xy+cyz*yz+czx*zx
    {0.28209479177387814f, 0,0,0, 0,0,0},
    {0.4886025119029199f,  0,0,0, 0,0,0},
    {0.4886025119029199f,  0,0,0, 0,0,0},
    {0.4886025119029199f,  0,0,0, 0,0,0},
    {0, 0,0,0, 1.0925484305920792f,0,0},
    {0, 0,0,0, 0,1.0925484305920792f,0},
    {0,-0.31539156525252005f,-0.31539156525252005f,0.6307831305050401f, 0,0,0},
    {0, 0,0,0, 0,0,1.0925484305920792f},
    {0, 0.5462742152960396f,-0.5462742152960396f,0, 0,0,0},
    {0, 1.7701307697799304f,-0.5900435899266435f,0, 0,0,0},
    {0, 0,0,0, 0,2.890611442640554f,0},
    {0,-0.4570457994644658f,-0.4570457994644658f,1.8281831978578632f, 0,0,0},
    {0,-1.1195289977703462f,-1.1195289977703462f,0.7463526651802308f, 0,0,0},
    {0,-0.4570457994644658f,-0.4570457994644658f,1.8281831978578632f, 0,0,0},
    {0, 1.445305721320277f,-1.445305721320277f,0, 0,0,0},
    {0, 0.5900435899266435f,-1.7701307697799304f,0, 0,0,0},
};

__constant__ int cLM2L[16] = {0,1,1,1, 2,2,2,2, 2,3,3,3, 3,3,3,3};

// -2 * log2(e): exp(-2 t^2) = exp2(K2E * t^2)
#define K2E (-2.8853900817779268f)

__global__ void __launch_bounds__(256) zero_out_kernel(float4* out, int n4) {
    int i = blockIdx.x * blockDim.x + threadIdx.x;
    int stride = gridDim.x * blockDim.x;
    float4 zv = make_float4(0.f, 0.f, 0.f, 0.f);
    for (; i < n4; i += stride) out[i] = zv;
}

__device__ __forceinline__ void red_f32(float* p, float v) {
    asm volatile("red.global.add.f32 [%0], %1;" :: "l"(p), "f"(v) : "memory");
}

__global__ void __launch_bounds__(256, 6) sph_expand_kernel(
    const float* __restrict__ dist,
    const float* __restrict__ dirs,      // [J,3]
    const float* __restrict__ centers,   // [32]
    const int*   __restrict__ zspec,     // [N_ATOMS]
    const int*   __restrict__ idx_i,     // [J]
    const int*   __restrict__ idx_j,     // [J]
    float*       __restrict__ out,       // [N_ATOMS*4*8*16]
    int J)
{
    const int lane  = threadIdx.x & 31;
    const int warp  = (blockIdx.x * blockDim.x + threadIdx.x) >> 5;
    const int nwarp = (gridDim.x * blockDim.x) >> 5;

    const int lm = lane & 15;
    const int h  = lane >> 4;            // parity of owned n
    const int l  = cLM2L[lm];

    // per-lane constants
    const float cen = centers[lane];     // lane as (l=lane>>3, n=lane&7)
    const float a0 = cA[lm][0], ax = cA[lm][1], ay = cA[lm][2], az = cA[lm][3];
    const float f0 = cF[lm][0], fx = cF[lm][1], fy = cF[lm][2], fz = cF[lm][3];
    const float fxy = cF[lm][4], fyz = cF[lm][5], fzx = cF[lm][6];

    // rb shuffle sources: rb[l][n] lives in lane 8*l+n; owned n = h+2k
    const int sR0 = 8*l + h;
    const int sR1 = sR0 + 2;
    const int sR2 = sR0 + 4;
    const int sR3 = sR0 + 6;

    float* const outLane = out + lane;   // float offset L within segment block
    const unsigned m = 0xffffffffu;

    const int npacks = J >> 2;
    const float4* __restrict__ dist4 = (const float4*)dist;
    const float4* __restrict__ dirs4 = (const float4*)dirs;
    const int4*   __restrict__ ii4p  = (const int4*)idx_i;
    const int4*   __restrict__ jj4p  = (const int4*)idx_j;

    for (int pk = warp; pk < npacks; pk += nwarp) {
        // ---- batch loads: 4 edges, 10 LDGs ----
        const float4 r4 = __ldg(dist4 + pk);
        const float4 d0 = __ldg(dirs4 + 3*pk + 0);
        const float4 d1 = __ldg(dirs4 + 3*pk + 1);
        const float4 d2 = __ldg(dirs4 + 3*pk + 2);
        const int4   i4 = __ldg(ii4p + pk);
        const int4   j4 = __ldg(jj4p + pk);

        const int z0 = __ldg(zspec + j4.x);
        const int z1 = __ldg(zspec + j4.y);
        const int z2 = __ldg(zspec + j4.z);
        const int z3 = __ldg(zspec + j4.w);

        const float rr[4]  = {r4.x, r4.y, r4.z, r4.w};
        const float xx[4]  = {d0.x, d0.w, d1.z, d2.y};
        const float yy[4]  = {d0.y, d1.x, d1.w, d2.z};
        const float zzv[4] = {d0.z, d1.y, d2.x, d2.w};
        const int  seg[4]  = {(i4.x<<2)+z0, (i4.y<<2)+z1, (i4.z<<2)+z2, (i4.w<<2)+z3};

        #pragma unroll
        for (int k = 0; k < 4; k++) {
            const float r = rr[k], x = xx[k], y = yy[k], zz = zzv[k];

            // branchless shifted-cosine cutoff (rc=5, w=0.5)
            const float u  = __saturatef((r - 4.5f) * 2.0f);
            const float fc = 0.5f + 0.5f * cospif(u);

            // radial basis for this lane's center (sigma=0.5 -> -2)
            const float t  = r - cen;
            const float rb = exp2f(K2E * t * t) * fc;

            // Y[lm] for this lane (fixed lm = lane&15)
            const float x2 = x*x, y2 = y*y, z2 = zz*zz;
            const float xy = x*y, yz = y*zz, zx = zz*x;
            const float f1 = a0 + ax*x + ay*y + az*zz;
            const float f2 = f0 + fx*x2 + fy*y2 + fz*z2 + fxy*xy + fyz*yz + fzx*zx;
            const float Y  = f1 * f2;

            // gather the 4 rb values (n = h, h+2, h+4, h+6)
            const float R0 = __shfl_sync(m, rb, sR0);
            const float R1 = __shfl_sync(m, rb, sR1);
            const float R2 = __shfl_sync(m, rb, sR2);
            const float R3 = __shfl_sync(m, rb, sR3);

            float* p = outLane + ((size_t)seg[k] << 7);
            red_f32(p,      Y * R0);
            red_f32(p + 32, Y * R1);
            red_f32(p + 64, Y * R2);
            red_f32(p + 96, Y * R3);
        }
    }

    // tail (J not a multiple of 4)
    for (int e = (npacks << 2) + warp; e < J; e += nwarp) {
        const float r  = __ldg(dist + e);
        const float x  = __ldg(dirs + 3*e + 0);
        const float y  = __ldg(dirs + 3*e + 1);
        const float zz = __ldg(dirs + 3*e + 2);
        const int   ii = __ldg(idx_i + e);
        const int   zj = __ldg(zspec + __ldg(idx_j + e));

        const float u  = __saturatef((r - 4.5f) * 2.0f);
        const float fc = 0.5f + 0.5f * cospif(u);
        const float t  = r - cen;
        const float rb = exp2f(K2E * t * t) * fc;

        const float x2 = x*x, y2 = y*y, z2 = zz*zz;
        const float xy = x*y, yz = y*zz, zx = zz*x;
        const float f1 = a0 + ax*x + ay*y + az*zz;
        const float f2 = f0 + fx*x2 + fy*y2 + fz*z2 + fxy*xy + fyz*yz + fzx*zx;
        const float Y  = f1 * f2;

        const float R0 = __shfl_sync(m, rb, sR0);
        const float R1 = __shfl_sync(m, rb, sR1);
        const float R2 = __shfl_sync(m, rb, sR2);
        const float R3 = __shfl_sync(m, rb, sR3);

        float* p = outLane + ((size_t)((ii << 2) + zj) << 7);
        red_f32(p,      Y * R0);
        red_f32(p + 32, Y * R1);
        red_f32(p + 64, Y * R2);
        red_f32(p + 96, Y * R3);
    }
}

extern "C" void kernel_launch(void* const* d_in, const int* in_sizes, int n_in,
                              void* d_out, int out_size) {
    const float* dist    = (const float*)d_in[0];
    const float* dirs    = (const float*)d_in[1];
    const float* centers = (const float*)d_in[2];
    const int*   zspec   = (const int*)d_in[3];
    const int*   idx_i   = (const int*)d_in[4];
    const int*   idx_j   = (const int*)d_in[5];
    float*       out     = (float*)d_out;
    const int J = in_sizes[0];

    const int n4 = out_size / 4;
    zero_out_kernel<<<1184, 256>>>((float4*)d_out, n4);

    const int blocks = 148 * 6;   // 6 blocks/SM (launch_bounds(256,6))
    sph_expand_kernel<<<blocks, 256>>>(dist, dirs, centers, zspec,
                                       idx_i, idx_j, out, J);
}

// round 8
// speedup vs baseline: 9.1650x; 9.1650x over previous
#include <cuda_runtime.h>
#include <cstdint>

// ---------------------------------------------------------------------------
// SphericalExpansion, round 8 = round 4 (verified 86.5us) + immediate-offset
// REDs. Launch config EXACTLY as R4: __launch_bounds__(256,5), grid 740.
//
// One WARP per 4-edge pack. Lane L:
//   - computes rb[k=L] = __expf(-2 (r-center_L)^2)*fc  (k = l*8+n)
//   - computes Y[lm=L&15] = f1*f2 (branchless coefficient tables)
//   - owns segment floats {L, L+32, L+64, L+96}: same lm = L&15 (own Y),
//     n = (L>>4)+2k -> 4 rb gathered via shfl.idx
//   - 4x red.global.add.f32 at [p], [p+128B], [p+256B], [p+384B] (immediate
//     offsets, one 128B wavefront each)
// Batch loads per pack: float4/int4 (10 LDGs for 4 edges).
// ---------------------------------------------------------------------------

__constant__ float cA[16][4] = {   // f1 = a0 + ax*x + ay*y + az*z (one-hot)
    {1,0,0,0}, {0,0,1,0}, {0,0,0,1}, {0,1,0,0},
    {1,0,0,0}, {1,0,0,0}, {1,0,0,0}, {1,0,0,0},
    {1,0,0,0}, {0,0,1,0}, {0,1,0,0}, {0,0,1,0},
    {0,0,0,1}, {0,1,0,0}, {0,0,0,1}, {0,1,0,0},
};

__constant__ float cF[16][7] = {   // f2 = c0+cx*x2+cy*y2+cz*z2+cxy*xy+cyz*yz+czx*zx
    {0.28209479177387814f, 0,0,0, 0,0,0},
    {0.4886025119029199f,  0,0,0, 0,0,0},
    {0.4886025119029199f,  0,0,0, 0,0,0},
    {0.4886025119029199f,  0,0,0, 0,0,0},
    {0, 0,0,0, 1.0925484305920792f,0,0},
    {0, 0,0,0, 0,1.0925484305920792f,0},
    {0,-0.31539156525252005f,-0.31539156525252005f,0.6307831305050401f, 0,0,0},
    {0, 0,0,0, 0,0,1.0925484305920792f},
    {0, 0.5462742152960396f,-0.5462742152960396f,0, 0,0,0},
    {0, 1.7701307697799304f,-0.5900435899266435f,0, 0,0,0},
    {0, 0,0,0, 0,2.890611442640554f,0},
    {0,-0.4570457994644658f,-0.4570457994644658f,1.8281831978578632f, 0,0,0},
    {0,-1.1195289977703462f,-1.1195289977703462f,0.7463526651802308f, 0,0,0},
    {0,-0.4570457994644658f,-0.4570457994644658f,1.8281831978578632f, 0,0,0},
    {0, 1.445305721320277f,-1.445305721320277f,0, 0,0,0},
    {0, 0.5900435899266435f,-1.7701307697799304f,0, 0,0,0},
};

__constant__ int cLM2L[16] = {0,1,1,1, 2,2,2,2, 2,3,3,3, 3,3,3,3};

__global__ void __launch_bounds__(256) zero_out_kernel(float4* out, int n4) {
    int i = blockIdx.x * blockDim.x + threadIdx.x;
    int stride = gridDim.x * blockDim.x;
    float4 zv = make_float4(0.f, 0.f, 0.f, 0.f);
    for (; i < n4; i += stride) out[i] = zv;
}

__device__ __forceinline__ void red4_f32(float* p, float v0, float v1,
                                         float v2, float v3) {
    asm volatile("red.global.add.f32 [%0], %1;"     :: "l"(p), "f"(v0) : "memory");
    asm volatile("red.global.add.f32 [%0+128], %1;" :: "l"(p), "f"(v1) : "memory");
    asm volatile("red.global.add.f32 [%0+256], %1;" :: "l"(p), "f"(v2) : "memory");
    asm volatile("red.global.add.f32 [%0+384], %1;" :: "l"(p), "f"(v3) : "memory");
}

__global__ void __launch_bounds__(256, 5) sph_expand_kernel(
    const float* __restrict__ dist,
    const float* __restrict__ dirs,      // [J,3]
    const float* __restrict__ centers,   // [32]
    const int*   __restrict__ zspec,     // [N_ATOMS]
    const int*   __restrict__ idx_i,     // [J]
    const int*   __restrict__ idx_j,     // [J]
    float*       __restrict__ out,       // [N_ATOMS*4*8*16]
    int J)
{
    const int lane  = threadIdx.x & 31;
    const int warp  = (blockIdx.x * blockDim.x + threadIdx.x) >> 5;
    const int nwarp = (gridDim.x * blockDim.x) >> 5;

    const int lm = lane & 15;
    const int h  = lane >> 4;            // parity of owned n
    const int l  = cLM2L[lm];

    // per-lane constants
    const float cen = centers[lane];     // lane as (l=lane>>3, n=lane&7)
    const float a0 = cA[lm][0], ax = cA[lm][1], ay = cA[lm][2], az = cA[lm][3];
    const float f0 = cF[lm][0], fx = cF[lm][1], fy = cF[lm][2], fz = cF[lm][3];
    const float fxy = cF[lm][4], fyz = cF[lm][5], fzx = cF[lm][6];

    // rb shuffle sources: rb[l][n] lives in lane 8*l+n; owned n = h+2k
    const int sR0 = 8*l + h;
    const int sR1 = sR0 + 2;
    const int sR2 = sR0 + 4;
    const int sR3 = sR0 + 6;

    float* const outLane = out + lane;   // float offset L within segment block
    const unsigned m = 0xffffffffu;

    const int npacks = J >> 2;
    const float4* __restrict__ dist4 = (const float4*)dist;
    const float4* __restrict__ dirs4 = (const float4*)dirs;
    const int4*   __restrict__ ii4p  = (const int4*)idx_i;
    const int4*   __restrict__ jj4p  = (const int4*)idx_j;

    for (int pk = warp; pk < npacks; pk += nwarp) {
        // ---- batch loads: 4 edges, 10 LDGs ----
        const float4 r4 = __ldg(dist4 + pk);
        const float4 d0 = __ldg(dirs4 + 3*pk + 0);
        const float4 d1 = __ldg(dirs4 + 3*pk + 1);
        const float4 d2 = __ldg(dirs4 + 3*pk + 2);
        const int4   i4 = __ldg(ii4p + pk);
        const int4   j4 = __ldg(jj4p + pk);

        const int z0 = __ldg(zspec + j4.x);
        const int z1 = __ldg(zspec + j4.y);
        const int z2 = __ldg(zspec + j4.z);
        const int z3 = __ldg(zspec + j4.w);

        const float rr[4]  = {r4.x, r4.y, r4.z, r4.w};
        const float xx[4]  = {d0.x, d0.w, d1.z, d2.y};
        const float yy[4]  = {d0.y, d1.x, d1.w, d2.z};
        const float zzv[4] = {d0.z, d1.y, d2.x, d2.w};
        const int  seg[4]  = {(i4.x<<2)+z0, (i4.y<<2)+z1, (i4.z<<2)+z2, (i4.w<<2)+z3};

        #pragma unroll
        for (int k = 0; k < 4; k++) {
            const float r = rr[k], x = xx[k], y = yy[k], zz = zzv[k];

            // branchless shifted-cosine cutoff (rc=5, w=0.5)
            const float u  = __saturatef((r - 4.5f) * 2.0f);
            const float fc = 0.5f + 0.5f * cospif(u);

            // radial basis for this lane's center (sigma=0.5 -> -2)
            const float t  = r - cen;
            const float rb = __expf(-2.0f * t * t) * fc;

            // Y[lm] for this lane (fixed lm = lane&15)
            const float x2 = x*x, y2 = y*y, z2 = zz*zz;
            const float xy = x*y, yz = y*zz, zx = zz*x;
            const float f1 = a0 + ax*x + ay*y + az*zz;
            const float f2 = f0 + fx*x2 + fy*y2 + fz*z2 + fxy*xy + fyz*yz + fzx*zx;
            const float Y  = f1 * f2;

            // gather the 4 rb values (n = h, h+2, h+4, h+6)
            const float R0 = __shfl_sync(m, rb, sR0);
            const float R1 = __shfl_sync(m, rb, sR1);
            const float R2 = __shfl_sync(m, rb, sR2);
            const float R3 = __shfl_sync(m, rb, sR3);

            float* p = outLane + ((size_t)seg[k] << 7);
            red4_f32(p, Y * R0, Y * R1, Y * R2, Y * R3);
        }
    }

    // tail (J not a multiple of 4)
    for (int e = (npacks << 2) + warp; e < J; e += nwarp) {
        const float r  = __ldg(dist + e);
        const float x  = __ldg(dirs + 3*e + 0);
        const float y  = __ldg(dirs + 3*e + 1);
        const float zz = __ldg(dirs + 3*e + 2);
        const int   ii = __ldg(idx_i + e);
        const int   zj = __ldg(zspec + __ldg(idx_j + e));

        const float u  = __saturatef((r - 4.5f) * 2.0f);
        const float fc = 0.5f + 0.5f * cospif(u);
        const float t  = r - cen;
        const float rb = __expf(-2.0f * t * t) * fc;

        const float x2 = x*x, y2 = y*y, z2 = zz*zz;
        const float xy = x*y, yz = y*zz, zx = zz*x;
        const float f1 = a0 + ax*x + ay*y + az*zz;
        const float f2 = f0 + fx*x2 + fy*y2 + fz*z2 + fxy*xy + fyz*yz + fzx*zx;
        const float Y  = f1 * f2;

        const float R0 = __shfl_sync(m, rb, sR0);
        const float R1 = __shfl_sync(m, rb, sR1);
        const float R2 = __shfl_sync(m, rb, sR2);
        const float R3 = __shfl_sync(m, rb, sR3);

        float* p = outLane + ((size_t)((ii << 2) + zj) << 7);
        red4_f32(p, Y * R0, Y * R1, Y * R2, Y * R3);
    }
}

extern "C" void kernel_launch(void* const* d_in, const int* in_sizes, int n_in,
                              void* d_out, int out_size) {
    const float* dist    = (const float*)d_in[0];
    const float* dirs    = (const float*)d_in[1];
    const float* centers = (const float*)d_in[2];
    const int*   zspec   = (const int*)d_in[3];
    const int*   idx_i   = (const int*)d_in[4];
    const int*   idx_j   = (const int*)d_in[5];
    float*       out     = (float*)d_out;
    const int J = in_sizes[0];

    const int n4 = out_size / 4;
    zero_out_kernel<<<1184, 256>>>((float4*)d_out, n4);

    const int blocks = 148 * 5;   // EXACT R4 launch config (verified 86.5us)
    sph_expand_kernel<<<blocks, 256>>>(dist, dirs, centers, zspec,
                                       idx_i, idx_j, out, J);
}

// round 9
// speedup vs baseline: 9.4301x; 1.0289x over previous
#include <cuda_runtime.h>
#include <cstdint>

// ---------------------------------------------------------------------------
// SphericalExpansion, round 9 = R8 structure + packed f32x2 math.
//
// Edges processed in packed PAIRS ("duos"): (x,y,z,r) of two edges share one
// 64-bit f32x2 register; Y polynomial + rb front-end execute once per duo
// via mul/add/fma.rn.f32x2 (sm_103a packed fp32, PTX-only).
// f2 rewritten without y^2 using x^2+y^2+z^2 = 1 (unit direction vectors).
// Ownership / shuffles / REDs identical to R8 (verified 86.5us):
//   lane L owns {L, L+32, L+64, L+96}; 4 rb shuffles; 4 scalar REDs.
// Launch: __launch_bounds__(256,4), grid 592  -- 64-reg headroom, NO spills
// (R6/R7 regressions were launch_bounds-induced local-memory spills).
// ---------------------------------------------------------------------------

typedef unsigned long long u64;

__constant__ float cA[16][4] = {   // f1 = a0 + ax*x + ay*y + az*z (one-hot)
    {1,0,0,0}, {0,0,1,0}, {0,0,0,1}, {0,1,0,0},
    {1,0,0,0}, {1,0,0,0}, {1,0,0,0}, {1,0,0,0},
    {1,0,0,0}, {0,0,1,0}, {0,1,0,0}, {0,0,1,0},
    {0,0,0,1}, {0,1,0,0}, {0,0,0,1}, {0,1,0,0},
};

// f2 = c0 + cx*x2 + cz*z2 + cxy*xy + cyz*yz + czx*zx   (y^2 eliminated via
// y^2 = 1 - x^2 - z^2; coefficients retabulated accordingly)
__constant__ float cF2[16][6] = {
    { 0.28209479177387814f, 0,0, 0,0,0},
    { 0.4886025119029199f,  0,0, 0,0,0},
    { 0.4886025119029199f,  0,0, 0,0,0},
    { 0.4886025119029199f,  0,0, 0,0,0},
    { 0, 0,0, 1.0925484305920792f,0,0},
    { 0, 0,0, 0,1.0925484305920792f,0},
    {-0.31539156525252005f, 0.0f,               0.9461746957575602f, 0,0,0},
    { 0, 0,0, 0,0,1.0925484305920792f},
    {-0.5462742152960396f,  1.0925484305920792f,0.5462742152960396f, 0,0,0},
    {-0.5900435899266435f,  2.360174359706574f, 0.5900435899266435f, 0,0,0},
    { 0, 0,0, 0,2.890611442640554f,0},
    {-0.4570457994644658f,  0.0f,               2.285228997322329f,  0,0,0},
    {-1.1195289977703462f,  0.0f,               1.865881662950577f,  0,0,0},
    {-0.4570457994644658f,  0.0f,               2.285228997322329f,  0,0,0},
    {-1.445305721320277f,   2.890611442640554f, 1.445305721320277f,  0,0,0},
    {-1.7701307697799304f,  2.360174359706574f, 1.7701307697799304f, 0,0,0},
};

__constant__ int cLM2L[16] = {0,1,1,1, 2,2,2,2, 2,3,3,3, 3,3,3,3};

#define K2E (-2.8853900817779268f)   // -2*log2(e): exp(-2 t^2) = exp2(K2E t^2)

// ---- packed f32x2 helpers (sm_103a) ----
__device__ __forceinline__ u64 pk2(float lo, float hi) {
    u64 r; asm("mov.b64 %0, {%1, %2};" : "=l"(r) : "f"(lo), "f"(hi)); return r;
}
__device__ __forceinline__ void upk2(float& lo, float& hi, u64 v) {
    asm("mov.b64 {%0, %1}, %2;" : "=f"(lo), "=f"(hi) : "l"(v));
}
__device__ __forceinline__ u64 mul2(u64 a, u64 b) {
    u64 r; asm("mul.rn.f32x2 %0, %1, %2;" : "=l"(r) : "l"(a), "l"(b)); return r;
}
__device__ __forceinline__ u64 add2(u64 a, u64 b) {
    u64 r; asm("add.rn.f32x2 %0, %1, %2;" : "=l"(r) : "l"(a), "l"(b)); return r;
}
__device__ __forceinline__ u64 fma2(u64 a, u64 b, u64 c) {
    u64 r; asm("fma.rn.f32x2 %0, %1, %2, %3;" : "=l"(r) : "l"(a), "l"(b), "l"(c)); return r;
}
__device__ __forceinline__ float ex2(float a) {
    float r; asm("ex2.approx.f32 %0, %1;" : "=f"(r) : "f"(a)); return r;
}

__global__ void __launch_bounds__(256) zero_out_kernel(float4* out, int n4) {
    int i = blockIdx.x * blockDim.x + threadIdx.x;
    int stride = gridDim.x * blockDim.x;
    float4 zv = make_float4(0.f, 0.f, 0.f, 0.f);
    for (; i < n4; i += stride) out[i] = zv;
}

__device__ __forceinline__ void red_f32(float* p, float v) {
    asm volatile("red.global.add.f32 [%0], %1;" :: "l"(p), "f"(v) : "memory");
}

__device__ __forceinline__ float cutoff(float r) {
    const float u = __saturatef((r - 4.5f) * 2.0f);
    return 0.5f + 0.5f * cospif(u);
}

__global__ void __launch_bounds__(256, 4) sph_expand_kernel(
    const float* __restrict__ dist,
    const float* __restrict__ dirs,      // [J,3]
    const float* __restrict__ centers,   // [32]
    const int*   __restrict__ zspec,     // [N_ATOMS]
    const int*   __restrict__ idx_i,     // [J]
    const int*   __restrict__ idx_j,     // [J]
    float*       __restrict__ out,       // [N_ATOMS*4*8*16]
    int J)
{
    const int lane  = threadIdx.x & 31;
    const int warp  = (blockIdx.x * blockDim.x + threadIdx.x) >> 5;
    const int nwarp = (gridDim.x * blockDim.x) >> 5;

    const int lm = lane & 15;
    const int h  = lane >> 4;            // parity of owned n
    const int l  = cLM2L[lm];

    // packed per-lane constants (each = (c, c))
    const float cenf = centers[lane];
    const u64 NEGCEN = pk2(-cenf, -cenf);
    const u64 KK  = pk2(K2E, K2E);
    const u64 A0  = pk2(cA[lm][0], cA[lm][0]);
    const u64 AX  = pk2(cA[lm][1], cA[lm][1]);
    const u64 AY  = pk2(cA[lm][2], cA[lm][2]);
    const u64 AZ  = pk2(cA[lm][3], cA[lm][3]);
    const u64 C0  = pk2(cF2[lm][0], cF2[lm][0]);
    const u64 CX  = pk2(cF2[lm][1], cF2[lm][1]);
    const u64 CZ  = pk2(cF2[lm][2], cF2[lm][2]);
    const u64 CXY = pk2(cF2[lm][3], cF2[lm][3]);
    const u64 CYZ = pk2(cF2[lm][4], cF2[lm][4]);
    const u64 CZX = pk2(cF2[lm][5], cF2[lm][5]);

    // rb shuffle sources: rb[l][n] lives in lane 8*l+n; owned n = h+2k
    const int sR0 = 8*l + h;
    const int sR1 = sR0 + 2;
    const int sR2 = sR0 + 4;
    const int sR3 = sR0 + 6;

    float* const outLane = out + lane;
    const unsigned m = 0xffffffffu;

    const int npacks = J >> 2;
    const float4* __restrict__ dist4 = (const float4*)dist;
    const float4* __restrict__ dirs4 = (const float4*)dirs;
    const int4*   __restrict__ ii4p  = (const int4*)idx_i;
    const int4*   __restrict__ jj4p  = (const int4*)idx_j;

    for (int pk = warp; pk < npacks; pk += nwarp) {
        // ---- batch loads: 4 edges, 10 LDGs ----
        const float4 r4 = __ldg(dist4 + pk);
        const float4 d0 = __ldg(dirs4 + 3*pk + 0);
        const float4 d1 = __ldg(dirs4 + 3*pk + 1);
        const float4 d2 = __ldg(dirs4 + 3*pk + 2);
        const int4   i4 = __ldg(ii4p + pk);
        const int4   j4 = __ldg(jj4p + pk);

        const int zs0 = __ldg(zspec + j4.x);
        const int zs1 = __ldg(zspec + j4.y);
        const int zs2 = __ldg(zspec + j4.z);
        const int zs3 = __ldg(zspec + j4.w);

        float* const pA = outLane + ((size_t)((i4.x << 2) + zs0) << 7);
        float* const pB = outLane + ((size_t)((i4.y << 2) + zs1) << 7);
        float* const pC = outLane + ((size_t)((i4.z << 2) + zs2) << 7);
        float* const pD = outLane + ((size_t)((i4.w << 2) + zs3) << 7);

        // duo layouts: (edge0,edge1) and (edge2,edge3)
        const u64 Rp[2]  = { pk2(r4.x, r4.y),  pk2(r4.z, r4.w) };
        const u64 Xp[2]  = { pk2(d0.x, d0.w),  pk2(d1.z, d2.y) };
        const u64 Yv[2]  = { pk2(d0.y, d1.x),  pk2(d1.w, d2.z) };
        const u64 Zp[2]  = { pk2(d0.z, d1.y),  pk2(d2.x, d2.w) };
        const float rsc[4] = { r4.x, r4.y, r4.z, r4.w };
        float* const ptr[4] = { pA, pB, pC, pD };

        #pragma unroll
        for (int d = 0; d < 2; d++) {
            // --- rb front-end, packed: arg = K2E * (r - cen)^2 ---
            const u64 T   = add2(Rp[d], NEGCEN);
            const u64 T2  = mul2(T, T);
            const u64 ARG = mul2(T2, KK);
            float a0f, a1f;  upk2(a0f, a1f, ARG);

            // scalar cutoffs + exp (MUFU)
            const float fc0 = cutoff(rsc[2*d + 0]);
            const float fc1 = cutoff(rsc[2*d + 1]);
            const float rb0 = ex2(a0f) * fc0;     // rb[k=lane] for edge 2d
            const float rb1 = ex2(a1f) * fc1;     // rb[k=lane] for edge 2d+1

            // --- Y polynomial, packed ---
            const u64 X2 = mul2(Xp[d], Xp[d]);
            const u64 Z2 = mul2(Zp[d], Zp[d]);
            const u64 XY = mul2(Xp[d], Yv[d]);
            const u64 YZ = mul2(Yv[d], Zp[d]);
            const u64 ZX = mul2(Zp[d], Xp[d]);
            const u64 f2p = fma2(CX, X2, fma2(CZ, Z2,
                             fma2(CXY, XY, fma2(CYZ, YZ, fma2(CZX, ZX, C0)))));
            const u64 f1p = fma2(AX, Xp[d], fma2(AY, Yv[d], fma2(AZ, Zp[d], A0)));
            const u64 Ypk = mul2(f1p, f2p);
            float y0, y1;  upk2(y0, y1, Ypk);

            // --- gather rb, scatter (scalar per edge, as R8) ---
            const float A0s = __shfl_sync(m, rb0, sR0);
            const float A1s = __shfl_sync(m, rb0, sR1);
            const float A2s = __shfl_sync(m, rb0, sR2);
            const float A3s = __shfl_sync(m, rb0, sR3);
            const float B0s = __shfl_sync(m, rb1, sR0);
            const float B1s = __shfl_sync(m, rb1, sR1);
            const float B2s = __shfl_sync(m, rb1, sR2);
            const float B3s = __shfl_sync(m, rb1, sR3);

            float* p0 = ptr[2*d + 0];
            float* p1 = ptr[2*d + 1];
            red_f32(p0,      y0 * A0s);
            red_f32(p0 + 32, y0 * A1s);
            red_f32(p0 + 64, y0 * A2s);
            red_f32(p0 + 96, y0 * A3s);
            red_f32(p1,      y1 * B0s);
            red_f32(p1 + 32, y1 * B1s);
            red_f32(p1 + 64, y1 * B2s);
            red_f32(p1 + 96, y1 * B3s);
        }
    }

    // tail (J not a multiple of 4) — cold scalar path, reads tables directly
    for (int e = (npacks << 2) + warp; e < J; e += nwarp) {
        const float r  = __ldg(dist + e);
        const float x  = __ldg(dirs + 3*e + 0);
        const float y  = __ldg(dirs + 3*e + 1);
        const float zz = __ldg(dirs + 3*e + 2);
        const int   ii = __ldg(idx_i + e);
        const int   zj = __ldg(zspec + __ldg(idx_j + e));

        const float fc = cutoff(r);
        const float t  = r - cenf;
        const float rb = ex2(K2E * t * t) * fc;

        const float x2 = x*x, z2 = zz*zz;
        const float xy = x*y, yz = y*zz, zx = zz*x;
        const float f1 = cA[lm][0] + cA[lm][1]*x + cA[lm][2]*y + cA[lm][3]*zz;
        const float f2v = cF2[lm][0] + cF2[lm][1]*x2 + cF2[lm][2]*z2
                        + cF2[lm][3]*xy + cF2[lm][4]*yz + cF2[lm][5]*zx;
        const float Y  = f1 * f2v;

        const float R0 = __shfl_sync(m, rb, sR0);
        const float R1 = __shfl_sync(m, rb, sR1);
        const float R2 = __shfl_sync(m, rb, sR2);
        const float R3 = __shfl_sync(m, rb, sR3);

        float* p = outLane + ((size_t)((ii << 2) + zj) << 7);
        red_f32(p,      Y * R0);
        red_f32(p + 32, Y * R1);
        red_f32(p + 64, Y * R2);
        red_f32(p + 96, Y * R3);
    }
}

extern "C" void kernel_launch(void* const* d_in, const int* in_sizes, int n_in,
                              void* d_out, int out_size) {
    const float* dist    = (const float*)d_in[0];
    const float* dirs    = (const float*)d_in[1];
    const float* centers = (const float*)d_in[2];
    const int*   zspec   = (const int*)d_in[3];
    const int*   idx_i   = (const int*)d_in[4];
    const int*   idx_j   = (const int*)d_in[5];
    float*       out     = (float*)d_out;
    const int J = in_sizes[0];

    const int n4 = out_size / 4;
    zero_out_kernel<<<1184, 256>>>((float4*)d_out, n4);

    const int blocks = 148 * 4;   // lb(256,4): 64-reg headroom, no spills
    sph_expand_kernel<<<blocks, 256>>>(dist, dirs, centers, zspec,
                                       idx_i, idx_j, out, J);
}